// round 4
// baseline (speedup 1.0000x reference)
#include <cuda_runtime.h>
#include <cstdint>

#define NN 10000
#define KK 32
#define FF 128
#define NR 300

typedef unsigned long long ull;

// scratch (no cudaMalloc allowed)
__device__ float g_pre[NN * FF];
__device__ float g_conv[NN * FF];

__device__ __forceinline__ ull pk2(float lo, float hi) {
    ull r;
    asm("mov.b64 %0, {%1, %2};" : "=l"(r)
        : "r"(__float_as_uint(lo)), "r"(__float_as_uint(hi)));
    return r;
}
__device__ __forceinline__ ull ffma2(ull a, ull b, ull c) {
    ull d;
    asm("fma.rn.f32x2 %0, %1, %2, %3;" : "=l"(d) : "l"(a), "l"(b), "l"(c));
    return d;
}
__device__ __forceinline__ float lo2(ull v) { return __uint_as_float((unsigned)v); }
__device__ __forceinline__ float hi2(ull v) { return __uint_as_float((unsigned)(v >> 32)); }

// shifted softplus: softplus(x) - ln2 = max(x,0) + log(0.5 + 0.5*exp(-|x|))
__device__ __forceinline__ float sspf(float x) {
    return fmaxf(x, 0.0f) + __logf(fmaf(0.5f, __expf(-fabsf(x)), 0.5f));
}

// ---------------------------------------------------------------------------
// pre = atomic @ W_pre + b_pre
// ---------------------------------------------------------------------------
__global__ void pre_kernel(const float* __restrict__ atomic,
                           const float* __restrict__ W,
                           const float* __restrict__ b) {
    __shared__ float row[FF];
    int i = blockIdx.x, f = threadIdx.x;
    row[f] = atomic[i * FF + f];
    __syncthreads();
    float acc = b[f];
#pragma unroll 8
    for (int c = 0; c < FF; c++) acc = fmaf(row[c], W[c * FF + f], acc);
    g_pre[i * FF + f] = acc;
}

// ---------------------------------------------------------------------------
// fused per-node: distances -> rbf -> ssp(rbf@Wc1) -> ssp(.@Wc2) -> masked
// reduce with gathered pre -> g_conv
// thread map: f2 = tid&63 owns feature pair (2*f2, 2*f2+1); kh = tid>>6 owns
// k-half [kh*16, kh*16+16). 64-bit f32x2 packed accumulators (16 per thread).
// rbf/h1 are stored lane-DUPLICATED in shared; loading rows as ulonglong2
// yields register-pair-aligned packed broadcast operands for fma.rn.f32x2
// with ZERO pack (mov.b64) instructions in the inner loops.
// ---------------------------------------------------------------------------
__global__ void __launch_bounds__(128, 2)
conv_kernel(const float* __restrict__ xyz, const float* __restrict__ emask,
            const int* __restrict__ src, const float* __restrict__ Wc1,
            const float* __restrict__ Wc2, const float* __restrict__ centers) {
    extern __shared__ float sm[];
    float* rbfd = sm;              // [32][600]  (each rbf value duplicated)
    float* h1d  = sm + 32 * 600;   // [32][256]  (each h1 value duplicated)
    __shared__ float d_sh[KK];
    __shared__ int   s_sh[KK];
    __shared__ float m_sh[KK];
    __shared__ ull   convp[128];

    const int i   = blockIdx.x;
    const int tid = threadIdx.x;
    const int f2  = tid & 63;
    const int kh  = tid >> 6;

    if (tid < KK) {
        int s = src[i * KK + tid];
        s_sh[tid] = s;
        float dx = xyz[3 * s + 0] - xyz[3 * i + 0];
        float dy = xyz[3 * s + 1] - xyz[3 * i + 1];
        float dz = xyz[3 * s + 2] - xyz[3 * i + 2];
        d_sh[tid] = sqrtf(dx * dx + dy * dy + dz * dz);
        m_sh[tid] = emask[i * KK + tid];
    }
    __syncthreads();

    // rbf: 32*300 values, duplicated into float2
    for (int idx = tid; idx < KK * NR; idx += 128) {
        int k = idx / NR;
        int r = idx - k * NR;
        float t = d_sh[k] - centers[r];
        float v = __expf(-10.0f * t * t);
        ((float2*)(rbfd + k * 600))[r] = make_float2(v, v);
    }
    __syncthreads();

    // ---- GEMM1: h1 = ssp(rbf @ Wc1) ----
    ull acc[16];
#pragma unroll
    for (int k = 0; k < 16; k++) acc[k] = 0ull;

    const ull* Wp = (const ull*)Wc1;  // [300][64] f32-pairs
    // rows of 150 ulonglong2 (each .x/.y is a duplicated broadcast pair)
    const ulonglong2* R = (const ulonglong2*)(rbfd + kh * 16 * 600);

    ull w00 = Wp[0 * 64 + f2], w01 = Wp[1 * 64 + f2];
    ull w10 = Wp[2 * 64 + f2], w11 = Wp[3 * 64 + f2];
#pragma unroll 1
    for (int r2 = 0; r2 < 150; r2 += 2) {
        int nr = (r2 + 2 < 150) ? (2 * (r2 + 2)) : 0;   // prefetch next group
        ull nw00 = Wp[(nr + 0) * 64 + f2];
        ull nw01 = Wp[(nr + 1) * 64 + f2];
        ull nw10 = Wp[(nr + 2) * 64 + f2];
        ull nw11 = Wp[(nr + 3) * 64 + f2];
#pragma unroll
        for (int k = 0; k < 16; k++) {
            ulonglong2 a = R[k * 150 + r2];
            ulonglong2 b = R[k * 150 + r2 + 1];
            acc[k] = ffma2(a.x, w00, acc[k]);
            acc[k] = ffma2(a.y, w01, acc[k]);
            acc[k] = ffma2(b.x, w10, acc[k]);
            acc[k] = ffma2(b.y, w11, acc[k]);
        }
        w00 = nw00; w01 = nw01; w10 = nw10; w11 = nw11;
    }

    // ssp + write h1 (duplicated)
#pragma unroll
    for (int k = 0; k < 16; k++) {
        float lo = sspf(lo2(acc[k]));
        float hi = sspf(hi2(acc[k]));
        float2* hp = (float2*)(h1d + (kh * 16 + k) * 256);
        hp[2 * f2 + 0] = make_float2(lo, lo);
        hp[2 * f2 + 1] = make_float2(hi, hi);
    }
    __syncthreads();

    // ---- GEMM2: filters = ssp(h1 @ Wc2) ----
#pragma unroll
    for (int k = 0; k < 16; k++) acc[k] = 0ull;
    const ull* W2p = (const ull*)Wc2;  // [128][64] f32-pairs
    // rows of 64 ulonglong2
    const ulonglong2* H = (const ulonglong2*)(h1d + kh * 16 * 256);

    ull v00 = W2p[0 * 64 + f2], v01 = W2p[1 * 64 + f2];
    ull v10 = W2p[2 * 64 + f2], v11 = W2p[3 * 64 + f2];
#pragma unroll 1
    for (int c2 = 0; c2 < 64; c2 += 2) {
        int nc = (c2 + 2 < 64) ? (2 * (c2 + 2)) : 0;
        ull nv00 = W2p[(nc + 0) * 64 + f2];
        ull nv01 = W2p[(nc + 1) * 64 + f2];
        ull nv10 = W2p[(nc + 2) * 64 + f2];
        ull nv11 = W2p[(nc + 3) * 64 + f2];
#pragma unroll
        for (int k = 0; k < 16; k++) {
            ulonglong2 a = H[k * 64 + c2];
            ulonglong2 b = H[k * 64 + c2 + 1];
            acc[k] = ffma2(a.x, v00, acc[k]);
            acc[k] = ffma2(a.y, v01, acc[k]);
            acc[k] = ffma2(b.x, v10, acc[k]);
            acc[k] = ffma2(b.y, v11, acc[k]);
        }
        v00 = nv00; v01 = nv01; v10 = nv10; v11 = nv11;
    }

    // ---- conv reduce: sum_k ssp(filters) * pre[src] * mask ----
    const ull* P = (const ull*)g_pre;
    ull conv = 0ull;
#pragma unroll
    for (int k = 0; k < 16; k++) {
        int kk = kh * 16 + k;
        float flo = sspf(lo2(acc[k]));
        float fhi = sspf(hi2(acc[k]));
        float m = m_sh[kk];
        ull pr = P[s_sh[kk] * 64 + f2];
        float plo = lo2(pr) * m;
        float phi = hi2(pr) * m;
        conv = ffma2(pk2(flo, fhi), pk2(plo, phi), conv);
    }
    convp[kh * 64 + f2] = conv;
    __syncthreads();
    if (tid < 64) {
        ull a = convp[tid];
        ull b = convp[64 + tid];
        ((float2*)(g_conv + i * FF))[tid] =
            make_float2(lo2(a) + lo2(b), hi2(a) + hi2(b));
    }
}

// ---------------------------------------------------------------------------
// out = atomic + ssp(conv @ W1 + b1) @ W2 + b2
// ---------------------------------------------------------------------------
__global__ void post_kernel(const float* __restrict__ atomic,
                            const float* __restrict__ W1,
                            const float* __restrict__ b1,
                            const float* __restrict__ W2,
                            const float* __restrict__ b2,
                            float* __restrict__ out) {
    __shared__ float row[FF];
    __shared__ float tt[FF];
    int i = blockIdx.x, f = threadIdx.x;
    row[f] = g_conv[i * FF + f];
    __syncthreads();
    float acc = b1[f];
#pragma unroll 8
    for (int c = 0; c < FF; c++) acc = fmaf(row[c], W1[c * FF + f], acc);
    tt[f] = sspf(acc);
    __syncthreads();
    float acc2 = b2[f];
#pragma unroll 8
    for (int c = 0; c < FF; c++) acc2 = fmaf(tt[c], W2[c * FF + f], acc2);
    out[i * FF + f] = atomic[i * FF + f] + acc2;
}

// ---------------------------------------------------------------------------
extern "C" void kernel_launch(void* const* d_in, const int* in_sizes, int n_in,
                              void* d_out, int out_size) {
    const float* xyz     = (const float*)d_in[0];
    const float* atomic  = (const float*)d_in[1];
    const float* emask   = (const float*)d_in[2];
    const int*   src     = (const int*)  d_in[3];
    const float* W_pre   = (const float*)d_in[4];
    const float* b_pre   = (const float*)d_in[5];
    const float* W_cf1   = (const float*)d_in[6];
    const float* W_cf2   = (const float*)d_in[7];
    const float* W_post1 = (const float*)d_in[8];
    const float* b_post1 = (const float*)d_in[9];
    const float* W_post2 = (const float*)d_in[10];
    const float* b_post2 = (const float*)d_in[11];
    const float* centers = (const float*)d_in[12];
    float* out = (float*)d_out;

    const int smem = (32 * 600 + 32 * 256) * 4;  // 109568 bytes
    cudaFuncSetAttribute(conv_kernel,
                         cudaFuncAttributeMaxDynamicSharedMemorySize, smem);

    pre_kernel<<<NN, FF>>>(atomic, W_pre, b_pre);
    conv_kernel<<<NN, 128, smem>>>(xyz, emask, src, W_cf1, W_cf2, centers);
    post_kernel<<<NN, FF>>>(atomic, W_post1, b_post1, W_post2, b_post2, out);
}

// round 5
// speedup vs baseline: 1.4010x; 1.4010x over previous
#include <cuda_runtime.h>
#include <cstdint>

#define NN 10000
#define KK 32
#define FF 128
#define NR 300

typedef unsigned long long ull;

// scratch (no cudaMalloc allowed)
__device__ float g_pre[NN * FF];
__device__ float g_conv[NN * FF];
__device__ ull g_Wp1[150 * FF];   // r-pair packed W_cf1: (W[2p][f], W[2p+1][f])
__device__ ull g_Wp2[64 * FF];    // r-pair packed W_cf2

__device__ __forceinline__ ull pk2(float lo, float hi) {
    ull r;
    asm("mov.b64 %0, {%1, %2};" : "=l"(r)
        : "r"(__float_as_uint(lo)), "r"(__float_as_uint(hi)));
    return r;
}
__device__ __forceinline__ ull ffma2(ull a, ull b, ull c) {
    ull d;
    asm("fma.rn.f32x2 %0, %1, %2, %3;" : "=l"(d) : "l"(a), "l"(b), "l"(c));
    return d;
}
__device__ __forceinline__ float lo2(ull v) { return __uint_as_float((unsigned)v); }
__device__ __forceinline__ float hi2(ull v) { return __uint_as_float((unsigned)(v >> 32)); }

// shifted softplus: softplus(x) - ln2 = max(x,0) + log(0.5 + 0.5*exp(-|x|))
__device__ __forceinline__ float sspf(float x) {
    return fmaxf(x, 0.0f) + __logf(fmaf(0.5f, __expf(-fabsf(x)), 0.5f));
}

// ---------------------------------------------------------------------------
// weight pre-pack: Wp[p][f] = (W[2p][f], W[2p+1][f]) as packed f32x2
// ---------------------------------------------------------------------------
__global__ void pack1_kernel(const float* __restrict__ W) {
    int p = blockIdx.x, f = threadIdx.x;
    g_Wp1[p * FF + f] = pk2(W[(2 * p) * FF + f], W[(2 * p + 1) * FF + f]);
}
__global__ void pack2_kernel(const float* __restrict__ W) {
    int p = blockIdx.x, f = threadIdx.x;
    g_Wp2[p * FF + f] = pk2(W[(2 * p) * FF + f], W[(2 * p + 1) * FF + f]);
}

// ---------------------------------------------------------------------------
// pre = atomic @ W_pre + b_pre
// ---------------------------------------------------------------------------
__global__ void pre_kernel(const float* __restrict__ atomic,
                           const float* __restrict__ W,
                           const float* __restrict__ b) {
    __shared__ float row[FF];
    int i = blockIdx.x, f = threadIdx.x;
    row[f] = atomic[i * FF + f];
    __syncthreads();
    float acc = b[f];
#pragma unroll 8
    for (int c = 0; c < FF; c++) acc = fmaf(row[c], W[c * FF + f], acc);
    g_pre[i * FF + f] = acc;
}

// ---------------------------------------------------------------------------
// fused per-node conv. Reduction-dim (r/c) packed FFMA2:
//   thread (fg = tid&63, kg = tid>>6) owns features {2fg, 2fg+1} x k-half kg.
//   acc0/acc1[k] are f32x2 pairs whose lo/hi accumulate even/odd r terms;
//   h1 = ssp(lo+hi). rbf/h1 stored PLAIN in smem (no duplication) ->
//   55 KB smem -> 3 CTAs/SM; ulonglong2 rbf loads give packed operands free.
// ---------------------------------------------------------------------------
#define RBF_ROW 304   // floats per rbf row (padded, 16B aligned)
#define H1_ROW  136   // floats per h1 row (padded, 16B aligned)

__global__ void __launch_bounds__(128, 3)
conv_kernel(const float* __restrict__ xyz, const float* __restrict__ emask,
            const int* __restrict__ src, const float* __restrict__ centers) {
    extern __shared__ float sm[];
    float* rbf = sm;                    // [32][304]
    float* h1  = sm + KK * RBF_ROW;     // [32][136]
    __shared__ float  d_sh[KK];
    __shared__ int    s_sh[KK];
    __shared__ float  m_sh[KK];
    __shared__ float2 part[128];

    const int i   = blockIdx.x;
    const int tid = threadIdx.x;
    const int fg  = tid & 63;
    const int kg  = tid >> 6;

    if (tid < KK) {
        int s = src[i * KK + tid];
        s_sh[tid] = s;
        float dx = xyz[3 * s + 0] - xyz[3 * i + 0];
        float dy = xyz[3 * s + 1] - xyz[3 * i + 1];
        float dz = xyz[3 * s + 2] - xyz[3 * i + 2];
        d_sh[tid] = sqrtf(dx * dx + dy * dy + dz * dz);
        m_sh[tid] = emask[i * KK + tid];
    }
    __syncthreads();

    // rbf fill (plain)
    for (int idx = tid; idx < KK * NR; idx += 128) {
        int k = idx / NR;
        int r = idx - k * NR;
        float t = d_sh[k] - centers[r];
        rbf[k * RBF_ROW + r] = __expf(-10.0f * t * t);
    }
    __syncthreads();

    // ---- GEMM1: h1 = ssp(rbf @ Wc1), r-packed ----
    ull acc0[16], acc1[16];
#pragma unroll
    for (int k = 0; k < 16; k++) { acc0[k] = 0ull; acc1[k] = 0ull; }

    const ulonglong2* W1v = (const ulonglong2*)g_Wp1;   // row p: 64 ulonglong2
    const char* rbase = (const char*)rbf + (kg * 16) * (RBF_ROW * 4);

    ulonglong2 w0 = W1v[0 * 64 + fg];
    ulonglong2 w1 = W1v[1 * 64 + fg];
#pragma unroll 1
    for (int g = 0; g < 75; g++) {
        int gn = (g + 1 < 75) ? (g + 1) : 0;            // prefetch next group
        ulonglong2 w0n = W1v[(2 * gn + 0) * 64 + fg];
        ulonglong2 w1n = W1v[(2 * gn + 1) * 64 + fg];
        const char* rb = rbase + g * 16;
#pragma unroll
        for (int k = 0; k < 16; k++) {
            ulonglong2 a = *(const ulonglong2*)(rb + k * (RBF_ROW * 4));
            acc0[k] = ffma2(a.x, w0.x, acc0[k]);
            acc1[k] = ffma2(a.x, w0.y, acc1[k]);
            acc0[k] = ffma2(a.y, w1.x, acc0[k]);
            acc1[k] = ffma2(a.y, w1.y, acc1[k]);
        }
        w0 = w0n; w1 = w1n;
    }

    // ssp + write h1 (plain, float2 per (k, feature-pair))
#pragma unroll
    for (int k = 0; k < 16; k++) {
        float v0 = sspf(lo2(acc0[k]) + hi2(acc0[k]));
        float v1 = sspf(lo2(acc1[k]) + hi2(acc1[k]));
        *(float2*)(h1 + (kg * 16 + k) * H1_ROW + 2 * fg) = make_float2(v0, v1);
    }
    __syncthreads();

    // ---- GEMM2: filters = ssp(h1 @ Wc2), c-packed ----
#pragma unroll
    for (int k = 0; k < 16; k++) { acc0[k] = 0ull; acc1[k] = 0ull; }

    const ulonglong2* W2v = (const ulonglong2*)g_Wp2;
    const char* hbase = (const char*)h1 + (kg * 16) * (H1_ROW * 4);

    ulonglong2 v0 = W2v[0 * 64 + fg];
    ulonglong2 v1 = W2v[1 * 64 + fg];
#pragma unroll 1
    for (int g = 0; g < 32; g++) {
        int gn = (g + 1 < 32) ? (g + 1) : 0;
        ulonglong2 v0n = W2v[(2 * gn + 0) * 64 + fg];
        ulonglong2 v1n = W2v[(2 * gn + 1) * 64 + fg];
        const char* hb = hbase + g * 16;
#pragma unroll
        for (int k = 0; k < 16; k++) {
            ulonglong2 a = *(const ulonglong2*)(hb + k * (H1_ROW * 4));
            acc0[k] = ffma2(a.x, v0.x, acc0[k]);
            acc1[k] = ffma2(a.x, v0.y, acc1[k]);
            acc0[k] = ffma2(a.y, v1.x, acc0[k]);
            acc1[k] = ffma2(a.y, v1.y, acc1[k]);
        }
        v0 = v0n; v1 = v1n;
    }

    // ---- conv reduce: sum_k ssp(filters) * pre[src] * mask ----
    float c0 = 0.0f, c1 = 0.0f;
#pragma unroll
    for (int k = 0; k < 16; k++) {
        int kk = kg * 16 + k;
        float f0 = sspf(lo2(acc0[k]) + hi2(acc0[k]));
        float f1 = sspf(lo2(acc1[k]) + hi2(acc1[k]));
        float2 p = *(const float2*)(g_pre + s_sh[kk] * FF + 2 * fg);
        float m = m_sh[kk];
        c0 = fmaf(f0, p.x * m, c0);
        c1 = fmaf(f1, p.y * m, c1);
    }
    part[tid] = make_float2(c0, c1);
    __syncthreads();
    if (tid < 64) {
        float2 a = part[tid];
        float2 b = part[tid + 64];
        *(float2*)(g_conv + i * FF + 2 * tid) = make_float2(a.x + b.x, a.y + b.y);
    }
}

// ---------------------------------------------------------------------------
// out = atomic + ssp(conv @ W1 + b1) @ W2 + b2
// ---------------------------------------------------------------------------
__global__ void post_kernel(const float* __restrict__ atomic,
                            const float* __restrict__ W1,
                            const float* __restrict__ b1,
                            const float* __restrict__ W2,
                            const float* __restrict__ b2,
                            float* __restrict__ out) {
    __shared__ float row[FF];
    __shared__ float tt[FF];
    int i = blockIdx.x, f = threadIdx.x;
    row[f] = g_conv[i * FF + f];
    __syncthreads();
    float acc = b1[f];
#pragma unroll 8
    for (int c = 0; c < FF; c++) acc = fmaf(row[c], W1[c * FF + f], acc);
    tt[f] = sspf(acc);
    __syncthreads();
    float acc2 = b2[f];
#pragma unroll 8
    for (int c = 0; c < FF; c++) acc2 = fmaf(tt[c], W2[c * FF + f], acc2);
    out[i * FF + f] = atomic[i * FF + f] + acc2;
}

// ---------------------------------------------------------------------------
extern "C" void kernel_launch(void* const* d_in, const int* in_sizes, int n_in,
                              void* d_out, int out_size) {
    const float* xyz     = (const float*)d_in[0];
    const float* atomic  = (const float*)d_in[1];
    const float* emask   = (const float*)d_in[2];
    const int*   src     = (const int*)  d_in[3];
    const float* W_pre   = (const float*)d_in[4];
    const float* b_pre   = (const float*)d_in[5];
    const float* W_cf1   = (const float*)d_in[6];
    const float* W_cf2   = (const float*)d_in[7];
    const float* W_post1 = (const float*)d_in[8];
    const float* b_post1 = (const float*)d_in[9];
    const float* W_post2 = (const float*)d_in[10];
    const float* b_post2 = (const float*)d_in[11];
    const float* centers = (const float*)d_in[12];
    float* out = (float*)d_out;

    const int smem = (KK * RBF_ROW + KK * H1_ROW) * 4;  // 56320 bytes
    cudaFuncSetAttribute(conv_kernel,
                         cudaFuncAttributeMaxDynamicSharedMemorySize, smem);

    pack1_kernel<<<150, FF>>>(W_cf1);
    pack2_kernel<<<64, FF>>>(W_cf2);
    pre_kernel<<<NN, FF>>>(atomic, W_pre, b_pre);
    conv_kernel<<<NN, 128, smem>>>(xyz, emask, src, centers);
    post_kernel<<<NN, FF>>>(atomic, W_post1, b_post1, W_post2, b_post2, out);
}

// round 16
// speedup vs baseline: 2.7872x; 1.9895x over previous
#include <cuda_runtime.h>
#include <cuda_bf16.h>
#include <cstdint>

#define NN 10000
#define KK 32
#define FF 128
#define NR 300
typedef unsigned long long ull;
typedef unsigned int u32;

// ---------------- scratch (no cudaMalloc allowed) ----------------
__device__ __align__(16) float g_pre[NN * FF];
__device__ __align__(16) float g_conv[NN * FF];
// pre-packed transposed weights, bf16 hi/lo planes, layout [chunk][plane][n][68]
__device__ uint4 g_B1[5 * 2176];
__device__ uint4 g_B2[2 * 2176];

#define KS 68            // padded row stride in bf16 (64 data + 4 pad)
#define ROWB (KS * 2)    // 136 bytes per row
#define PLANEB 17408     // 128 * 136 bytes per plane buffer
#define SM_B1 34816      // B1 planes at [34816, 69632)
#define SM_B2 69632      // B2 staged chunk planes at [69632, 104448)
#define SMEM_DYN 104448

__device__ __forceinline__ float sspf(float x) {
    return fmaxf(x, 0.0f) + __logf(fmaf(0.5f, __expf(-fabsf(x)), 0.5f));
}
__device__ __forceinline__ u32 pack_bf2(float a, float b) {
    __nv_bfloat16 ha = __float2bfloat16(a), hb = __float2bfloat16(b);
    return (u32)__bfloat16_as_ushort(ha) | ((u32)__bfloat16_as_ushort(hb) << 16);
}
// m16n8k16 row.col bf16 -> f32 acc
__device__ __forceinline__ void mma16816(float* c, const u32* a, u32 b0, u32 b1) {
    asm volatile(
        "mma.sync.aligned.m16n8k16.row.col.f32.bf16.bf16.f32 "
        "{%0,%1,%2,%3}, {%4,%5,%6,%7}, {%8,%9}, {%0,%1,%2,%3};"
        : "+f"(c[0]), "+f"(c[1]), "+f"(c[2]), "+f"(c[3])
        : "r"(a[0]), "r"(a[1]), "r"(a[2]), "r"(a[3]), "r"(b0), "r"(b1));
}

// ---------------- weight pre-pack: Bs[n][k] = W[k][n], hi/lo planes ------
__global__ void packB1_kernel(const float* __restrict__ W) {
    int kc = blockIdx.x >> 7, n = blockIdx.x & 127, k = threadIdx.x;  // block 64
    int kg = kc * 64 + k;
    float v = (kg < NR) ? W[kg * FF + n] : 0.0f;
    __nv_bfloat16 h = __float2bfloat16(v);
    __nv_bfloat16 l = __float2bfloat16(v - __bfloat162float(h));
    __nv_bfloat16* base = (__nv_bfloat16*)g_B1;
    base[(kc * 2 + 0) * 8704 + n * KS + k] = h;
    base[(kc * 2 + 1) * 8704 + n * KS + k] = l;
}
__global__ void packB2_kernel(const float* __restrict__ W) {
    int kc = blockIdx.x >> 7, n = blockIdx.x & 127, k = threadIdx.x;
    int kg = kc * 64 + k;
    float v = W[kg * FF + n];
    __nv_bfloat16 h = __float2bfloat16(v);
    __nv_bfloat16 l = __float2bfloat16(v - __bfloat162float(h));
    __nv_bfloat16* base = (__nv_bfloat16*)g_B2;
    base[(kc * 2 + 0) * 8704 + n * KS + k] = h;
    base[(kc * 2 + 1) * 8704 + n * KS + k] = l;
}

// ---------------- pre = atomic @ W_pre + b_pre ----------------
__global__ void pre_kernel(const float* __restrict__ atomic,
                           const float* __restrict__ W,
                           const float* __restrict__ b) {
    __shared__ float row[FF];
    int i = blockIdx.x, f = threadIdx.x;
    row[f] = atomic[i * FF + f];
    __syncthreads();
    float acc = b[f];
#pragma unroll 8
    for (int c = 0; c < FF; c++) acc = fmaf(row[c], W[c * FF + f], acc);
    g_pre[i * FF + f] = acc;
}

// ---------------- fused conv: 4 nodes/CTA, mma.sync bf16 3-pass ----------
// warp (nd = wid>>1, nhalf = wid&1): 32x64 tile; rows = (node nd, neighbor j),
// cols = features [nhalf*64, +64). Fragment mapping per PTX m16n8k16 spec.
__global__ void __launch_bounds__(256, 2)
conv_kernel(const float* __restrict__ xyz, const float* __restrict__ emask,
            const int* __restrict__ src, const float* __restrict__ centers) {
    extern __shared__ char smb[];
    __shared__ float d_sh[128], m_sh[128];
    __shared__ int   s_sh[128];
    __shared__ float cent[320];

    const int tid = threadIdx.x;
    const int lane = tid & 31, wid = tid >> 5;
    const int g = lane >> 2, t = lane & 3;
    const int nd = wid >> 1, nhalf = wid & 1;
    const int warpM = nd * 32, nbase = nhalf * 64;
    const int i4 = blockIdx.x * 4;

    if (tid < 128) {
        int node = tid >> 5, j = tid & 31;
        int s = src[(i4 + node) * KK + j];
        s_sh[tid] = s;
        float dx = xyz[3 * s + 0] - xyz[3 * (i4 + node) + 0];
        float dy = xyz[3 * s + 1] - xyz[3 * (i4 + node) + 1];
        float dz = xyz[3 * s + 2] - xyz[3 * (i4 + node) + 2];
        d_sh[tid] = sqrtf(dx * dx + dy * dy + dz * dz);
        m_sh[tid] = emask[(i4 + node) * KK + j];
    }
    for (int j = tid; j < 320; j += 256) cent[j] = (j < NR) ? centers[j] : 0.0f;
    __syncthreads();

    float acc[2][8][4];
#pragma unroll
    for (int mb = 0; mb < 2; mb++)
#pragma unroll
        for (int nb = 0; nb < 8; nb++)
#pragma unroll
            for (int q = 0; q < 4; q++) acc[mb][nb][q] = 0.0f;

    // ---- GEMM1: h1_pre = rbf @ W1 (K = 320 in 5 chunks of 64) ----
    for (int kc = 0; kc < 5; kc++) {
        // fill A (rbf chunk): 128 rows x 32 k-pairs
        for (int p = tid; p < 4096; p += 256) {
            int row = p >> 5, kp = p & 31;
            int cg = kc * 64 + kp * 2;
            float v0 = 0.0f, v1 = 0.0f;
            if (cg < NR) {
                float d = d_sh[row];
                float t0 = d - cent[cg], t1 = d - cent[cg + 1];
                v0 = __expf(-10.0f * t0 * t0);
                v1 = __expf(-10.0f * t1 * t1);
            }
            __nv_bfloat16 h0 = __float2bfloat16(v0), h1 = __float2bfloat16(v1);
            float l0 = v0 - __bfloat162float(h0), l1 = v1 - __bfloat162float(h1);
            int off = row * ROWB + kp * 4;
            *(u32*)(smb + off) =
                (u32)__bfloat16_as_ushort(h0) | ((u32)__bfloat16_as_ushort(h1) << 16);
            *(u32*)(smb + PLANEB + off) = pack_bf2(l0, l1);
        }
        // copy B1 chunk (both planes, 2176 uint4)
        {
            const uint4* s = g_B1 + kc * 2176;
            uint4* dst = (uint4*)(smb + SM_B1);
            for (int j = tid; j < 2176; j += 256) dst[j] = s[j];
        }
        __syncthreads();
#pragma unroll
        for (int cs = 0; cs < 4; cs++) {
            const int kk = cs * 16;
            u32 aH[2][4], aL[2][4];
#pragma unroll
            for (int mb = 0; mb < 2; mb++) {
                int base = (warpM + mb * 16 + g) * ROWB + (kk + t * 2) * 2;
                aH[mb][0] = *(const u32*)(smb + base);
                aH[mb][1] = *(const u32*)(smb + base + 8 * ROWB);
                aH[mb][2] = *(const u32*)(smb + base + 16);
                aH[mb][3] = *(const u32*)(smb + base + 8 * ROWB + 16);
                aL[mb][0] = *(const u32*)(smb + PLANEB + base);
                aL[mb][1] = *(const u32*)(smb + PLANEB + base + 8 * ROWB);
                aL[mb][2] = *(const u32*)(smb + PLANEB + base + 16);
                aL[mb][3] = *(const u32*)(smb + PLANEB + base + 8 * ROWB + 16);
            }
#pragma unroll
            for (int nb = 0; nb < 8; nb++) {
                int bb = SM_B1 + (nbase + nb * 8 + g) * ROWB + (kk + t * 2) * 2;
                u32 bH0 = *(const u32*)(smb + bb);
                u32 bH1 = *(const u32*)(smb + bb + 16);
                u32 bL0 = *(const u32*)(smb + bb + PLANEB);
                u32 bL1 = *(const u32*)(smb + bb + PLANEB + 16);
#pragma unroll
                for (int mb = 0; mb < 2; mb++) {
                    mma16816(acc[mb][nb], aH[mb], bH0, bH1);
                    mma16816(acc[mb][nb], aH[mb], bL0, bL1);
                    mma16816(acc[mb][nb], aL[mb], bH0, bH1);
                }
            }
        }
        __syncthreads();  // protect A1/B1 reuse (and A2 overlay after last chunk)
    }

    // ---- epilogue 1: h1 = ssp(acc) -> A2 overlay [plane][chunk][row][KS] ----
    // A2 plane p chunk c at (p*2+c)*PLANEB; this warp's cols live in chunk=nhalf.
#pragma unroll
    for (int mb = 0; mb < 2; mb++) {
#pragma unroll
        for (int nb = 0; nb < 8; nb++) {
            int r0 = warpM + mb * 16 + g, r1 = r0 + 8;
            int kin = nb * 8 + t * 2;
            float v00 = sspf(acc[mb][nb][0]), v01 = sspf(acc[mb][nb][1]);
            float v10 = sspf(acc[mb][nb][2]), v11 = sspf(acc[mb][nb][3]);
            __nv_bfloat16 h00 = __float2bfloat16(v00), h01 = __float2bfloat16(v01);
            __nv_bfloat16 h10 = __float2bfloat16(v10), h11 = __float2bfloat16(v11);
            float l00 = v00 - __bfloat162float(h00), l01 = v01 - __bfloat162float(h01);
            float l10 = v10 - __bfloat162float(h10), l11 = v11 - __bfloat162float(h11);
            int hiB = nhalf * PLANEB, loB = (2 + nhalf) * PLANEB;
            *(u32*)(smb + hiB + r0 * ROWB + kin * 2) =
                (u32)__bfloat16_as_ushort(h00) | ((u32)__bfloat16_as_ushort(h01) << 16);
            *(u32*)(smb + hiB + r1 * ROWB + kin * 2) =
                (u32)__bfloat16_as_ushort(h10) | ((u32)__bfloat16_as_ushort(h11) << 16);
            *(u32*)(smb + loB + r0 * ROWB + kin * 2) = pack_bf2(l00, l01);
            *(u32*)(smb + loB + r1 * ROWB + kin * 2) = pack_bf2(l10, l11);
        }
    }
    __syncthreads();

    // reset accumulators for GEMM2
#pragma unroll
    for (int mb = 0; mb < 2; mb++)
#pragma unroll
        for (int nb = 0; nb < 8; nb++)
#pragma unroll
            for (int q = 0; q < 4; q++) acc[mb][nb][q] = 0.0f;

    // ---- GEMM2: D2 = h1 @ W2 (K = 128 in 2 staged chunks of 64) ----
    for (int c2 = 0; c2 < 2; c2++) {
        {
            const uint4* s = g_B2 + c2 * 2176;
            uint4* dst = (uint4*)(smb + SM_B2);
            for (int j = tid; j < 2176; j += 256) dst[j] = s[j];
        }
        __syncthreads();
#pragma unroll
        for (int cs = 0; cs < 4; cs++) {
            const int kk = cs * 16;
            u32 aH[2][4], aL[2][4];
#pragma unroll
            for (int mb = 0; mb < 2; mb++) {
                int base = (warpM + mb * 16 + g) * ROWB + (kk + t * 2) * 2;
                int hiB = c2 * PLANEB, loB = (2 + c2) * PLANEB;
                aH[mb][0] = *(const u32*)(smb + hiB + base);
                aH[mb][1] = *(const u32*)(smb + hiB + base + 8 * ROWB);
                aH[mb][2] = *(const u32*)(smb + hiB + base + 16);
                aH[mb][3] = *(const u32*)(smb + hiB + base + 8 * ROWB + 16);
                aL[mb][0] = *(const u32*)(smb + loB + base);
                aL[mb][1] = *(const u32*)(smb + loB + base + 8 * ROWB);
                aL[mb][2] = *(const u32*)(smb + loB + base + 16);
                aL[mb][3] = *(const u32*)(smb + loB + base + 8 * ROWB + 16);
            }
#pragma unroll
            for (int nb = 0; nb < 8; nb++) {
                int bb = SM_B2 + (nbase + nb * 8 + g) * ROWB + (kk + t * 2) * 2;
                u32 bH0 = *(const u32*)(smb + bb);
                u32 bH1 = *(const u32*)(smb + bb + 16);
                u32 bL0 = *(const u32*)(smb + bb + PLANEB);
                u32 bL1 = *(const u32*)(smb + bb + PLANEB + 16);
#pragma unroll
                for (int mb = 0; mb < 2; mb++) {
                    mma16816(acc[mb][nb], aH[mb], bH0, bH1);
                    mma16816(acc[mb][nb], aH[mb], bL0, bL1);
                    mma16816(acc[mb][nb], aL[mb], bH0, bH1);
                }
            }
        }
        __syncthreads();  // protect B2 restage
    }

    // ---- epilogue 2: conv[nd][f] = sum_j ssp(D2[j][f]) * pre[src]*mask ----
#pragma unroll
    for (int nb = 0; nb < 8; nb++) {
        int f0 = nbase + nb * 8 + t * 2;
        float s0 = 0.0f, s1 = 0.0f;
#pragma unroll
        for (int mb = 0; mb < 2; mb++) {
            int kA = mb * 16 + g, kB = kA + 8;
            float mA = m_sh[warpM + kA], mB = m_sh[warpM + kB];
            float2 pA = *(const float2*)(g_pre + s_sh[warpM + kA] * FF + f0);
            float2 pB = *(const float2*)(g_pre + s_sh[warpM + kB] * FF + f0);
            s0 += sspf(acc[mb][nb][0]) * pA.x * mA + sspf(acc[mb][nb][2]) * pB.x * mB;
            s1 += sspf(acc[mb][nb][1]) * pA.y * mA + sspf(acc[mb][nb][3]) * pB.y * mB;
        }
        s0 += __shfl_xor_sync(0xffffffffu, s0, 4);
        s0 += __shfl_xor_sync(0xffffffffu, s0, 8);
        s0 += __shfl_xor_sync(0xffffffffu, s0, 16);
        s1 += __shfl_xor_sync(0xffffffffu, s1, 4);
        s1 += __shfl_xor_sync(0xffffffffu, s1, 8);
        s1 += __shfl_xor_sync(0xffffffffu, s1, 16);
        if (lane < 4)
            *(float2*)(g_conv + (i4 + nd) * FF + f0) = make_float2(s0, s1);
    }
}

// ---------------- post: out = atomic + ssp(conv@W1+b1)@W2 + b2 ----------
__global__ void post_kernel(const float* __restrict__ atomic,
                            const float* __restrict__ W1,
                            const float* __restrict__ b1,
                            const float* __restrict__ W2,
                            const float* __restrict__ b2,
                            float* __restrict__ out) {
    __shared__ float row[FF];
    __shared__ float tt[FF];
    int i = blockIdx.x, f = threadIdx.x;
    row[f] = g_conv[i * FF + f];
    __syncthreads();
    float acc = b1[f];
#pragma unroll 8
    for (int c = 0; c < FF; c++) acc = fmaf(row[c], W1[c * FF + f], acc);
    tt[f] = sspf(acc);
    __syncthreads();
    float acc2 = b2[f];
#pragma unroll 8
    for (int c = 0; c < FF; c++) acc2 = fmaf(tt[c], W2[c * FF + f], acc2);
    out[i * FF + f] = atomic[i * FF + f] + acc2;
}

// ---------------------------------------------------------------------------
extern "C" void kernel_launch(void* const* d_in, const int* in_sizes, int n_in,
                              void* d_out, int out_size) {
    const float* xyz     = (const float*)d_in[0];
    const float* atomic  = (const float*)d_in[1];
    const float* emask   = (const float*)d_in[2];
    const int*   src     = (const int*)  d_in[3];
    const float* W_pre   = (const float*)d_in[4];
    const float* b_pre   = (const float*)d_in[5];
    const float* W_cf1   = (const float*)d_in[6];
    const float* W_cf2   = (const float*)d_in[7];
    const float* W_post1 = (const float*)d_in[8];
    const float* b_post1 = (const float*)d_in[9];
    const float* W_post2 = (const float*)d_in[10];
    const float* b_post2 = (const float*)d_in[11];
    const float* centers = (const float*)d_in[12];
    float* out = (float*)d_out;

    cudaFuncSetAttribute(conv_kernel,
                         cudaFuncAttributeMaxDynamicSharedMemorySize, SMEM_DYN);

    packB1_kernel<<<5 * 128, 64>>>(W_cf1);
    packB2_kernel<<<2 * 128, 64>>>(W_cf2);
    pre_kernel<<<NN, FF>>>(atomic, W_pre, b_pre);
    conv_kernel<<<NN / 4, 256, SMEM_DYN>>>(xyz, emask, src, centers);
    post_kernel<<<NN, FF>>>(atomic, W_post1, b_post1, W_post2, b_post2, out);
}